// round 3
// baseline (speedup 1.0000x reference)
#include <cuda_runtime.h>
#include <cuda_bf16.h>

#define N_NODES 50000
#define N_EDGES 500000
#define H 128
#define G_GRAPHS 100
#define NPG 500
#define NPROT 400
#define PN 35
#define LN 11
#define NLAYERS 4
#define EPS 1e-5f
#define NE_TILE 64
#define TP 66   // transposed smem row pad (floats)

// ---------------- scratch ----------------
__device__ float g_h[N_NODES * H];
__device__ float g_P1[N_NODES * H];
__device__ float g_P2[N_NODES * H];
__device__ float g_agg[N_NODES * H];
__device__ float g_U[N_NODES * H];
__device__ float g_pos[N_NODES * 3];
__device__ float g_posdelta[N_NODES * 3];
__device__ float g_deg[N_NODES];
__device__ float g_bnstats[2 * H];
__device__ float g_gfeat[G_GRAPHS * 2 * H];
// sorted-edge structures (rebuilt every launch)
__device__ int g_rowcur[N_NODES];
__device__ int g_srow[N_EDGES];
__device__ int g_scol[N_EDGES];
__device__ int g_sperm[N_EDGES];

__device__ __forceinline__ float silu_f(float x) {
    return x / (1.f + __expf(-x));
}

// ---- packed f32x2 helpers ----
__device__ __forceinline__ unsigned long long fma2(unsigned long long a,
                                                   unsigned long long b,
                                                   unsigned long long c) {
    unsigned long long d;
    asm("fma.rn.f32x2 %0, %1, %2, %3;" : "=l"(d) : "l"(a), "l"(b), "l"(c));
    return d;
}
__device__ __forceinline__ unsigned long long dup2(float x) {
    unsigned long long d;
    unsigned int xi = __float_as_uint(x);
    asm("mov.b64 %0, {%1, %1};" : "=l"(d) : "r"(xi));
    return d;
}
__device__ __forceinline__ float2 unpack2(unsigned long long v) {
    unsigned int lo, hi;
    asm("mov.b64 {%0, %1}, %2;" : "=r"(lo), "=r"(hi) : "l"(v));
    float2 r;
    r.x = __uint_as_float(lo);
    r.y = __uint_as_float(hi);
    return r;
}

// ---------------- K1: embed (also zeroes deg / bnstats accumulators) ----------------
__global__ void k_embed(const float* __restrict__ x, const float* __restrict__ pos_in,
                        const float* __restrict__ Wp, const float* __restrict__ bp,
                        const float* __restrict__ Wl, const float* __restrict__ bl) {
    __shared__ float xs[PN];
    const int i = blockIdx.x;
    const int t = threadIdx.x;
    if (t < PN) xs[t] = x[i * PN + t];
    if (t == 0) g_deg[i] = 0.f;
    if (t < 3) g_pos[i * 3 + t] = pos_in[i * 3 + t];
    if (i == 0 && t < H) { g_bnstats[t] = 0.f; g_bnstats[H + t] = 0.f; }
    __syncthreads();
    const bool isp = (i % NPG) < NPROT;
    const float* W = isp ? Wp : Wl;
    const float* b = isp ? bp : bl;
    const int nk = isp ? PN : LN;
    float acc = b[t];
    for (int k = 0; k < nk; k++) acc += xs[k] * W[k * H + t];
    g_h[i * H + t] = acc;
}

// ---------------- K2: bnstats + degree (fused via blockIdx split) ----------------
#define DEG_BLOCKS ((N_EDGES + 511) / 512)
__global__ __launch_bounds__(512) void k_stats_deg(const int* __restrict__ ei) {
    const int t = threadIdx.x;
    if (blockIdx.x < 256) {
        const int j = t & 127;
        const int g2 = t >> 7;
        float s = 0.f, s2 = 0.f;
        for (int i = blockIdx.x * 4 + g2; i < N_NODES; i += 1024) {
            float v = g_h[i * H + j];
            s += v; s2 += v * v;
        }
        atomicAdd(&g_bnstats[j], s);
        atomicAdd(&g_bnstats[H + j], s2);
    } else {
        const int e = (blockIdx.x - 256) * 512 + t;
        if (e < N_EDGES) atomicAdd(&g_deg[ei[e]], 1.0f);
    }
}

// ---------------- K3: bnapply + degree exclusive scan (single extra block) ----------------
#define BNA_BLOCKS ((N_NODES * H) / 512)
__global__ __launch_bounds__(512) void k_bnapply_scan(const float* __restrict__ gamma,
                                                      const float* __restrict__ beta) {
    const int t = threadIdx.x;
    if (blockIdx.x < BNA_BLOCKS) {
        const int idx = blockIdx.x * 512 + t;
        const int j = idx & (H - 1);
        const float inv_n = 1.f / (float)N_NODES;
        float mu = g_bnstats[j] * inv_n;
        float var = g_bnstats[H + j] * inv_n - mu * mu;
        g_h[idx] = (g_h[idx] - mu) * rsqrtf(var + EPS) * gamma[j] + beta[j];
    } else {
        // exclusive scan of degrees -> g_rowcur (counting-sort write cursors)
        __shared__ int sums[512];
        const int chunk = 98;   // 512*98 >= 50000
        int base = t * chunk;
        int lim = min(base + chunk, N_NODES);
        int s = 0;
        for (int i = base; i < lim; i++) s += (int)g_deg[i];
        sums[t] = s;
        __syncthreads();
        for (int off = 1; off < 512; off <<= 1) {
            int v = (t >= off) ? sums[t - off] : 0;
            __syncthreads();
            sums[t] += v;
            __syncthreads();
        }
        int run = (t == 0) ? 0 : sums[t - 1];
        for (int i = base; i < lim; i++) {
            g_rowcur[i] = run;
            run += (int)g_deg[i];
        }
    }
}

// ---------------- K5: counting-sort scatter ----------------
__global__ __launch_bounds__(512) void k_perm(const int* __restrict__ ei) {
    const int e = blockIdx.x * 512 + threadIdx.x;
    if (e >= N_EDGES) return;
    int r = ei[e];
    int p = atomicAdd(&g_rowcur[r], 1);
    g_srow[p] = r;
    g_scol[p] = ei[N_EDGES + e];
    g_sperm[p] = e;
}

// ---------------- per-layer node projection (FFMA2) ----------------
__global__ __launch_bounds__(512, 1) void k_proj(const float* __restrict__ w,
                                                 const float* __restrict__ b1) {
    extern __shared__ float sm[];
    float* w_s = sm;            // [128][256]
    float* a_t = sm + 32768;    // [128 k][TP]
    const int t = threadIdx.x;
    const int n0 = blockIdx.x * 64;

    for (int i = t; i < 32768; i += 512) {
        int k = i >> 8, jj = i & 255;
        int srcrow = (jj < 128) ? k : (128 + k);
        w_s[i] = w[srcrow * H + (jj & 127)];
    }
    for (int i = t; i < 8192; i += 512) {
        int n = i >> 7, k = i & 127;
        int gi = n0 + n;
        a_t[k * TP + n] = (gi < N_NODES) ? g_h[gi * H + k] : 0.f;
    }
    for (int i = t; i < 64 * H; i += 512) {
        int gi = n0 + (i >> 7);
        if (gi < N_NODES) g_agg[gi * H + (i & 127)] = 0.f;
    }
    if (t < 192) {
        int gi = n0 + t / 3;
        if (gi < N_NODES) g_posdelta[gi * 3 + t % 3] = 0.f;
    }
    __syncthreads();

    const int j0 = (t & 127) * 2;
    const int eh = t >> 7;
    const int nb = eh * 16;
    unsigned long long acc0[8], acc1[8];
#pragma unroll
    for (int p = 0; p < 8; p++) { acc0[p] = 0ull; acc1[p] = 0ull; }

#pragma unroll 2
    for (int k = 0; k < 128; k++) {
        float2 wp = *(const float2*)&w_s[k * 256 + j0];
        unsigned long long bd0 = dup2(wp.x), bd1 = dup2(wp.y);
        const float* ar = &a_t[k * TP + nb];
#pragma unroll
        for (int p = 0; p < 8; p++) {
            unsigned long long av = *(const unsigned long long*)&ar[2 * p];
            acc0[p] = fma2(av, bd0, acc0[p]);
            acc1[p] = fma2(av, bd1, acc1[p]);
        }
    }

    const int half = j0 >> 7;
    const int j = j0 & 127;
    float* outp = half ? g_P2 : g_P1;
    const float bb0 = half ? 0.f : b1[j];
    const float bb1 = half ? 0.f : b1[j + 1];
#pragma unroll
    for (int p = 0; p < 8; p++) {
        float2 a0 = unpack2(acc0[p]);
        float2 a1 = unpack2(acc1[p]);
        int n0g = n0 + nb + 2 * p;
        if (n0g < N_NODES) {
            float2 v = make_float2(a0.x + bb0, a1.x + bb1);
            *(float2*)&outp[n0g * H + j] = v;
        }
        if (n0g + 1 < N_NODES) {
            float2 v = make_float2(a0.y + bb0, a1.y + bb1);
            *(float2*)&outp[(n0g + 1) * H + j] = v;
        }
    }
}

// ---------------- fused edge kernel on SORTED edges ----------------
__global__ __launch_bounds__(512, 1) void k_edge(
    const float* __restrict__ eattr,
    const float* __restrict__ w2, const float* __restrict__ b2,
    const float* __restrict__ cw1, const float* __restrict__ cb1,
    const float* __restrict__ cw2, const float* __restrict__ ew1) {
    extern __shared__ float sm[];
    float* w2_s  = sm;                // 16384
    float* c1_s  = w2_s + 16384;      // 16384
    float* b2_s  = c1_s + 16384;      // 128
    float* cb1_s = b2_s + 128;        // 128
    float* c2_s  = cb1_s + 128;       // 128
    float* wd2_s = c2_s + 128;        // 128
    float* wea_s = wd2_s + 128;       // 512
    float* hid_t = wea_s + 512;       // [128][TP]
    float* m_t   = hid_t + 128 * TP;  // [128][TP]
    float* d2_s  = m_t + 128 * TP;    // 64
    float* rel_s = d2_s + 64;         // 192
    float* ea_s  = rel_s + 192;       // 256
    float* wsum_s = ea_s + 256;       // 64
    float* wred  = wsum_s + 64;       // 128
    int* row_s = (int*)(wred + 128);  // 64
    int* col_s = row_s + 64;          // 64

    const int t = threadIdx.x;
    for (int i = t; i < 16384; i += 512) { w2_s[i] = w2[i]; c1_s[i] = cw1[i]; }
    if (t < 128) {
        b2_s[t] = b2[t]; cb1_s[t] = cb1[t]; c2_s[t] = cw2[t];
        wd2_s[t] = ew1[256 * H + t];
    }
    if (t < 512) wea_s[t] = ew1[257 * H + t];
    __syncthreads();

    const int j0 = (t & 63) * 2;
    const int eh = t >> 6;
    const int ebase = eh * 8;
    const int ntiles = (N_EDGES + NE_TILE - 1) / NE_TILE;

    for (int tile = blockIdx.x; tile < ntiles; tile += gridDim.x) {
        const int e0 = tile * NE_TILE;
        if (t < NE_TILE) {
            int sidx = e0 + t;
            int r = -1, c = 0, pe = 0;
            if (sidx < N_EDGES) { r = g_srow[sidx]; c = g_scol[sidx]; pe = g_sperm[sidx]; }
            row_s[t] = r; col_s[t] = c;
            float4 a = make_float4(0.f, 0.f, 0.f, 0.f);
            if (r >= 0) a = *(const float4*)&eattr[pe * 4];
            int rr = r < 0 ? 0 : r;
            float rx = g_pos[rr * 3 + 0] - g_pos[c * 3 + 0];
            float ry = g_pos[rr * 3 + 1] - g_pos[c * 3 + 1];
            float rz = g_pos[rr * 3 + 2] - g_pos[c * 3 + 2];
            rel_s[t * 3 + 0] = rx; rel_s[t * 3 + 1] = ry; rel_s[t * 3 + 2] = rz;
            d2_s[t] = rx * rx + ry * ry + rz * rz;
            ea_s[t * 4 + 0] = a.x; ea_s[t * 4 + 1] = a.y;
            ea_s[t * 4 + 2] = a.z; ea_s[t * 4 + 3] = a.w;
        }
        __syncthreads();

        // Phase A: hidden (transposed store; sorted rows -> L1-friendly P1 gathers)
#pragma unroll
        for (int rep = 0; rep < 16; rep++) {
            int idx = t + rep * 512;
            int e = idx >> 7, j = idx & 127;
            int r = row_s[e], c = col_s[e];
            int rr = r < 0 ? 0 : r;
            float v = g_P1[rr * H + j] + g_P2[c * H + j] + d2_s[e] * wd2_s[j];
#pragma unroll
            for (int a2 = 0; a2 < 4; a2++) v += ea_s[e * 4 + a2] * wea_s[a2 * H + j];
            hid_t[j * TP + e] = silu_f(v);
        }
        __syncthreads();

        // Phase B: m = silu(hid @ W2 + b2)
        {
            unsigned long long acc0[4], acc1[4];
#pragma unroll
            for (int p = 0; p < 4; p++) { acc0[p] = 0ull; acc1[p] = 0ull; }
#pragma unroll 4
            for (int k = 0; k < 128; k++) {
                float2 wp = *(const float2*)&w2_s[k * H + j0];
                unsigned long long bd0 = dup2(wp.x), bd1 = dup2(wp.y);
                const float* hr = &hid_t[k * TP + ebase];
#pragma unroll
                for (int p = 0; p < 4; p++) {
                    unsigned long long av = *(const unsigned long long*)&hr[2 * p];
                    acc0[p] = fma2(av, bd0, acc0[p]);
                    acc1[p] = fma2(av, bd1, acc1[p]);
                }
            }
            float b0 = b2_s[j0], b1v = b2_s[j0 + 1];
#pragma unroll
            for (int p = 0; p < 4; p++) {
                float2 a0 = unpack2(acc0[p]);
                float2 a1 = unpack2(acc1[p]);
                float2 o0 = make_float2(silu_f(a0.x + b0), silu_f(a0.y + b0));
                float2 o1 = make_float2(silu_f(a1.x + b1v), silu_f(a1.y + b1v));
                *(float2*)&m_t[j0 * TP + ebase + 2 * p] = o0;
                *(float2*)&m_t[(j0 + 1) * TP + ebase + 2 * p] = o1;
            }
        }
        __syncthreads();

        // Phase C: w = silu(m@C1 + cb1) @ C2
        {
            unsigned long long acc0[4], acc1[4];
#pragma unroll
            for (int p = 0; p < 4; p++) { acc0[p] = 0ull; acc1[p] = 0ull; }
#pragma unroll 4
            for (int k = 0; k < 128; k++) {
                float2 wp = *(const float2*)&c1_s[k * H + j0];
                unsigned long long bd0 = dup2(wp.x), bd1 = dup2(wp.y);
                const float* mr = &m_t[k * TP + ebase];
#pragma unroll
                for (int p = 0; p < 4; p++) {
                    unsigned long long av = *(const unsigned long long*)&mr[2 * p];
                    acc0[p] = fma2(av, bd0, acc0[p]);
                    acc1[p] = fma2(av, bd1, acc1[p]);
                }
            }
            float cb0 = cb1_s[j0], cb1v = cb1_s[j0 + 1];
            float c20 = c2_s[j0], c21 = c2_s[j0 + 1];
            float part[8];
#pragma unroll
            for (int p = 0; p < 4; p++) {
                float2 a0 = unpack2(acc0[p]);
                float2 a1 = unpack2(acc1[p]);
                part[2 * p]     = silu_f(a0.x + cb0) * c20 + silu_f(a1.x + cb1v) * c21;
                part[2 * p + 1] = silu_f(a0.y + cb0) * c20 + silu_f(a1.y + cb1v) * c21;
            }
#pragma unroll
            for (int off = 16; off > 0; off >>= 1) {
#pragma unroll
                for (int e = 0; e < 8; e++)
                    part[e] += __shfl_xor_sync(0xffffffffu, part[e], off);
            }
            if ((t & 31) == 0) {
                int wsel = (t >> 5) & 1;
#pragma unroll
                for (int e = 0; e < 8; e++) wred[(ebase + e) * 2 + wsel] = part[e];
            }
        }
        __syncthreads();
        if (t < 64) wsum_s[t] = wred[t * 2] + wred[t * 2 + 1];
        __syncthreads();

        // Phase D: segment-scan scatter (sorted rows -> 1 coalesced atomic per run)
        {
            const int j = t & 127;
            const int q = t >> 7;           // 0..3, 16 edges each; uniform per warp
            const int ebeg = q * 16;
            float acc = 0.f;
            int cur = row_s[ebeg];
#pragma unroll
            for (int i = 0; i < 16; i++) {
                int e = ebeg + i;
                int r = row_s[e];
                float v = m_t[j * TP + e];
                if (r != cur) {
                    if (cur >= 0) atomicAdd(&g_agg[cur * H + j], acc);
                    acc = 0.f;
                    cur = r;
                }
                acc += v;
            }
            if (cur >= 0) atomicAdd(&g_agg[cur * H + j], acc);
        }
        if (t < 192) {
            int e = t / 3, k = t % 3;
            int r = row_s[e];
            if (r >= 0)
                atomicAdd(&g_posdelta[r * 3 + k], rel_s[e * 3 + k] * wsum_s[e]);
        }
        __syncthreads();
    }
}

// ---------------- pos update ----------------
__global__ void k_pos() {
    const int idx = blockIdx.x * blockDim.x + threadIdx.x;
    if (idx >= N_NODES * 3) return;
    const int i = idx / 3;
    float d = fmaxf(g_deg[i], 1.0f);
    g_pos[idx] += g_posdelta[idx] / d;
}

// ---------------- node stage 1 ----------------
__global__ __launch_bounds__(512, 1) void k_node1(const float* __restrict__ w,
                                                  const float* __restrict__ b) {
    extern __shared__ float sm[];
    float* w_s = sm;
    float* a_t = sm + 32768;
    const int t = threadIdx.x;
    const int n0 = blockIdx.x * 64;
    for (int i = t; i < 32768; i += 512) w_s[i] = w[i];
    for (int i = t; i < 16384; i += 512) {
        int n = i >> 8, k = i & 255;
        int gi = n0 + n;
        float v = 0.f;
        if (gi < N_NODES) v = (k < 128) ? g_h[gi * H + k] : g_agg[gi * H + (k - 128)];
        a_t[k * TP + n] = v;
    }
    __syncthreads();

    const int j0 = (t & 63) * 2;
    const int eh = t >> 6;
    const int nb = eh * 8;
    unsigned long long acc0[4], acc1[4];
#pragma unroll
    for (int p = 0; p < 4; p++) { acc0[p] = 0ull; acc1[p] = 0ull; }
#pragma unroll 4
    for (int k = 0; k < 256; k++) {
        float2 wp = *(const float2*)&w_s[k * H + j0];
        unsigned long long bd0 = dup2(wp.x), bd1 = dup2(wp.y);
        const float* ar = &a_t[k * TP + nb];
#pragma unroll
        for (int p = 0; p < 4; p++) {
            unsigned long long av = *(const unsigned long long*)&ar[2 * p];
            acc0[p] = fma2(av, bd0, acc0[p]);
            acc1[p] = fma2(av, bd1, acc1[p]);
        }
    }
    float b0 = b[j0], b1v = b[j0 + 1];
#pragma unroll
    for (int p = 0; p < 4; p++) {
        float2 a0 = unpack2(acc0[p]);
        float2 a1 = unpack2(acc1[p]);
        int n0g = n0 + nb + 2 * p;
        if (n0g < N_NODES) {
            float2 u = make_float2(silu_f(a0.x + b0), silu_f(a1.x + b1v));
            *(float2*)&g_U[n0g * H + j0] = u;
        }
        if (n0g + 1 < N_NODES) {
            float2 u = make_float2(silu_f(a0.y + b0), silu_f(a1.y + b1v));
            *(float2*)&g_U[(n0g + 1) * H + j0] = u;
        }
    }
}

// ---------------- node stage 2 ----------------
__global__ __launch_bounds__(512, 1) void k_node2(const float* __restrict__ w,
                                                  const float* __restrict__ b) {
    extern __shared__ float sm[];
    float* w_s = sm;
    float* a_t = sm + 16384;
    const int t = threadIdx.x;
    const int n0 = blockIdx.x * 64;
    for (int i = t; i < 16384; i += 512) w_s[i] = w[i];
    for (int i = t; i < 8192; i += 512) {
        int n = i >> 7, k = i & 127;
        int gi = n0 + n;
        a_t[k * TP + n] = (gi < N_NODES) ? g_U[gi * H + k] : 0.f;
    }
    __syncthreads();

    const int j0 = (t & 63) * 2;
    const int eh = t >> 6;
    const int nb = eh * 8;
    unsigned long long acc0[4], acc1[4];
#pragma unroll
    for (int p = 0; p < 4; p++) { acc0[p] = 0ull; acc1[p] = 0ull; }
#pragma unroll 4
    for (int k = 0; k < 128; k++) {
        float2 wp = *(const float2*)&w_s[k * H + j0];
        unsigned long long bd0 = dup2(wp.x), bd1 = dup2(wp.y);
        const float* ar = &a_t[k * TP + nb];
#pragma unroll
        for (int p = 0; p < 4; p++) {
            unsigned long long av = *(const unsigned long long*)&ar[2 * p];
            acc0[p] = fma2(av, bd0, acc0[p]);
            acc1[p] = fma2(av, bd1, acc1[p]);
        }
    }
    float b0 = b[j0], b1v = b[j0 + 1];
#pragma unroll
    for (int p = 0; p < 4; p++) {
        float2 a0 = unpack2(acc0[p]);
        float2 a1 = unpack2(acc1[p]);
        int n0g = n0 + nb + 2 * p;
        if (n0g < N_NODES) {
            float2 hv = *(float2*)&g_h[n0g * H + j0];
            hv.x += a0.x + b0; hv.y += a1.x + b1v;
            *(float2*)&g_h[n0g * H + j0] = hv;
        }
        if (n0g + 1 < N_NODES) {
            float2 hv = *(float2*)&g_h[(n0g + 1) * H + j0];
            hv.x += a0.y + b0; hv.y += a1.y + b1v;
            *(float2*)&g_h[(n0g + 1) * H + j0] = hv;
        }
    }
}

// ---------------- pooling ----------------
__global__ __launch_bounds__(512) void k_pool() {
    __shared__ float red[512];
    const int g = blockIdx.x, t = threadIdx.x;
    const int j = t & 127, w = t >> 7;
    float s = 0.f;
    for (int n = w; n < NPG; n += 4) s += g_h[(g * NPG + n) * H + j];
    red[t] = s;
    __syncthreads();
    if (w == 0) {
        float tot = red[j] + red[128 + j] + red[256 + j] + red[384 + j];
        g_gfeat[g * 256 + j] = tot;
        g_gfeat[g * 256 + 128 + j] = tot * (1.f / (float)NPG);
    }
}

// ---------------- readout head ----------------
__global__ void k_head(const float* __restrict__ h1_w, const float* __restrict__ h1_b,
                       const float* __restrict__ h2_w, const float* __restrict__ h2_b,
                       const float* __restrict__ h3_w, const float* __restrict__ h3_b,
                       float* __restrict__ out) {
    __shared__ float gf[256], z1[128], z2[64];
    const int g = blockIdx.x, t = threadIdx.x;
    gf[t] = g_gfeat[g * 256 + t];
    gf[128 + t] = g_gfeat[g * 256 + 128 + t];
    __syncthreads();
    float a = h1_b[t];
    for (int k = 0; k < 256; k++) a += gf[k] * h1_w[k * 128 + t];
    z1[t] = fmaxf(a, 0.f);
    __syncthreads();
    if (t < 64) {
        float a2 = h2_b[t];
        for (int k = 0; k < 128; k++) a2 += z1[k] * h2_w[k * 64 + t];
        z2[t] = fmaxf(a2, 0.f);
    }
    __syncthreads();
    if (t == 0) {
        float a3 = h3_b[0];
        for (int k = 0; k < 64; k++) a3 += z2[k] * h3_w[k];
        out[g] = a3;
    }
}

// ---------------- launch ----------------
extern "C" void kernel_launch(void* const* d_in, const int* in_sizes, int n_in,
                              void* d_out, int out_size) {
    const float* x     = (const float*)d_in[0];
    const float* pos   = (const float*)d_in[1];
    const int*   ei    = (const int*)d_in[2];
    const float* eattr = (const float*)d_in[3];
    const float* Wp    = (const float*)d_in[6];
    const float* bp    = (const float*)d_in[7];
    const float* Wl    = (const float*)d_in[8];
    const float* bl    = (const float*)d_in[9];
    const float* gamma = (const float*)d_in[10];
    const float* beta  = (const float*)d_in[11];
    const float* e_w1  = (const float*)d_in[12];
    const float* e_b1  = (const float*)d_in[13];
    const float* e_w2  = (const float*)d_in[14];
    const float* e_b2  = (const float*)d_in[15];
    const float* c_w1  = (const float*)d_in[16];
    const float* c_b1  = (const float*)d_in[17];
    const float* c_w2  = (const float*)d_in[18];
    const float* n_w1  = (const float*)d_in[19];
    const float* n_b1  = (const float*)d_in[20];
    const float* n_w2  = (const float*)d_in[21];
    const float* n_b2  = (const float*)d_in[22];
    const float* h1_w  = (const float*)d_in[23];
    const float* h1_b  = (const float*)d_in[24];
    const float* h2_w  = (const float*)d_in[25];
    const float* h2_b  = (const float*)d_in[26];
    const float* h3_w  = (const float*)d_in[27];
    const float* h3_b  = (const float*)d_in[28];
    float* out = (float*)d_out;

    const int PROJ_SMEM = (32768 + 128 * TP) * 4;
    const int EDGE_SMEM = (16384 * 2 + 128 * 5 + 512 + 2 * 128 * TP
                           + 64 + 192 + 256 + 64 + 128 + 128) * 4;
    const int N1_SMEM = (32768 + 256 * TP) * 4;
    const int N2_SMEM = (16384 + 128 * TP) * 4;
    cudaFuncSetAttribute(k_proj,  cudaFuncAttributeMaxDynamicSharedMemorySize, PROJ_SMEM);
    cudaFuncSetAttribute(k_edge,  cudaFuncAttributeMaxDynamicSharedMemorySize, EDGE_SMEM);
    cudaFuncSetAttribute(k_node1, cudaFuncAttributeMaxDynamicSharedMemorySize, N1_SMEM);
    cudaFuncSetAttribute(k_node2, cudaFuncAttributeMaxDynamicSharedMemorySize, N2_SMEM);

    const int nblocks64 = (N_NODES + 63) / 64;   // 782

    // 1: embed  2: bnstats+deg  3: bnapply+scan  4: proj L0  5: perm  6: edge L0
    k_embed<<<N_NODES, 128>>>(x, pos, Wp, bp, Wl, bl);
    k_stats_deg<<<256 + DEG_BLOCKS, 512>>>(ei);
    k_bnapply_scan<<<BNA_BLOCKS + 1, 512>>>(gamma, beta);

    for (int l = 0; l < NLAYERS; l++) {
        k_proj<<<nblocks64, 512, PROJ_SMEM>>>(e_w1 + l * 261 * H, e_b1 + l * H);
        if (l == 0) k_perm<<<(N_EDGES + 511) / 512, 512>>>(ei);
        k_edge<<<148, 512, EDGE_SMEM>>>(eattr,
                                        e_w2 + l * H * H, e_b2 + l * H,
                                        c_w1 + l * H * H, c_b1 + l * H,
                                        c_w2 + l * H, e_w1 + l * 261 * H);
        k_node1<<<nblocks64, 512, N1_SMEM>>>(n_w1 + l * 256 * H, n_b1 + l * H);
        k_node2<<<nblocks64, 512, N2_SMEM>>>(n_w2 + l * H * H, n_b2 + l * H);
        k_pos<<<(N_NODES * 3 + 511) / 512, 512>>>();
    }

    k_pool<<<G_GRAPHS, 512>>>();
    k_head<<<G_GRAPHS, 128>>>(h1_w, h1_b, h2_w, h2_b, h3_w, h3_b, out);
}

// round 4
// speedup vs baseline: 1.0408x; 1.0408x over previous
#include <cuda_runtime.h>
#include <cuda_bf16.h>

#define N_NODES 50000
#define N_EDGES 500000
#define H 128
#define G_GRAPHS 100
#define NPG 500
#define NPROT 400
#define PN 35
#define LN 11
#define NLAYERS 4
#define EPS 1e-5f
#define NE_TILE 64
#define TP 66   // transposed smem row pad (floats)

// ---------------- scratch ----------------
__device__ float g_h[N_NODES * H];
__device__ float g_P1[N_NODES * H];
__device__ float g_P2[N_NODES * H];
__device__ float g_agg[N_NODES * H];
__device__ float g_U[N_NODES * H];
__device__ float g_pos[N_NODES * 3];
__device__ float g_posdelta[N_NODES * 3];
__device__ float g_deg[N_NODES];
__device__ float g_bnstats[2 * H];
__device__ float g_gfeat[G_GRAPHS * 2 * H];
__device__ int g_rowcur[N_NODES];
__device__ int g_srow[N_EDGES];
__device__ int g_scol[N_EDGES];
__device__ int g_sperm[N_EDGES];

__device__ __forceinline__ float silu_f(float x) {
    return x / (1.f + __expf(-x));
}

// ---- packed f32x2 helpers ----
__device__ __forceinline__ unsigned long long fma2(unsigned long long a,
                                                   unsigned long long b,
                                                   unsigned long long c) {
    unsigned long long d;
    asm("fma.rn.f32x2 %0, %1, %2, %3;" : "=l"(d) : "l"(a), "l"(b), "l"(c));
    return d;
}
__device__ __forceinline__ unsigned long long dup2(float x) {
    unsigned long long d;
    unsigned int xi = __float_as_uint(x);
    asm("mov.b64 %0, {%1, %1};" : "=l"(d) : "r"(xi));
    return d;
}
__device__ __forceinline__ float2 unpack2(unsigned long long v) {
    unsigned int lo, hi;
    asm("mov.b64 {%0, %1}, %2;" : "=r"(lo), "=r"(hi) : "l"(v));
    float2 r;
    r.x = __uint_as_float(lo);
    r.y = __uint_as_float(hi);
    return r;
}

// ---------------- K1: embed ----------------
__global__ void k_embed(const float* __restrict__ x, const float* __restrict__ pos_in,
                        const float* __restrict__ Wp, const float* __restrict__ bp,
                        const float* __restrict__ Wl, const float* __restrict__ bl) {
    __shared__ float xs[PN];
    const int i = blockIdx.x;
    const int t = threadIdx.x;
    if (t < PN) xs[t] = x[i * PN + t];
    if (t == 0) g_deg[i] = 0.f;
    if (t < 3) g_pos[i * 3 + t] = pos_in[i * 3 + t];
    if (i == 0 && t < H) { g_bnstats[t] = 0.f; g_bnstats[H + t] = 0.f; }
    __syncthreads();
    const bool isp = (i % NPG) < NPROT;
    const float* W = isp ? Wp : Wl;
    const float* b = isp ? bp : bl;
    const int nk = isp ? PN : LN;
    float acc = b[t];
    for (int k = 0; k < nk; k++) acc += xs[k] * W[k * H + t];
    g_h[i * H + t] = acc;
}

// ---------------- K2: bnstats + degree ----------------
#define DEG_BLOCKS ((N_EDGES + 511) / 512)
__global__ __launch_bounds__(512) void k_stats_deg(const int* __restrict__ ei) {
    const int t = threadIdx.x;
    if (blockIdx.x < 256) {
        const int j = t & 127;
        const int g2 = t >> 7;
        float s = 0.f, s2 = 0.f;
        for (int i = blockIdx.x * 4 + g2; i < N_NODES; i += 1024) {
            float v = g_h[i * H + j];
            s += v; s2 += v * v;
        }
        atomicAdd(&g_bnstats[j], s);
        atomicAdd(&g_bnstats[H + j], s2);
    } else {
        const int e = (blockIdx.x - 256) * 512 + t;
        if (e < N_EDGES) atomicAdd(&g_deg[ei[e]], 1.0f);
    }
}

// ---------------- K3: bnapply + degree scan ----------------
#define BNA_BLOCKS ((N_NODES * H) / 512)
__global__ __launch_bounds__(512) void k_bnapply_scan(const float* __restrict__ gamma,
                                                      const float* __restrict__ beta) {
    const int t = threadIdx.x;
    if (blockIdx.x < BNA_BLOCKS) {
        const int idx = blockIdx.x * 512 + t;
        const int j = idx & (H - 1);
        const float inv_n = 1.f / (float)N_NODES;
        float mu = g_bnstats[j] * inv_n;
        float var = g_bnstats[H + j] * inv_n - mu * mu;
        g_h[idx] = (g_h[idx] - mu) * rsqrtf(var + EPS) * gamma[j] + beta[j];
    } else {
        __shared__ int sums[512];
        const int chunk = 98;
        int base = t * chunk;
        int lim = min(base + chunk, N_NODES);
        int s = 0;
        for (int i = base; i < lim; i++) s += (int)g_deg[i];
        sums[t] = s;
        __syncthreads();
        for (int off = 1; off < 512; off <<= 1) {
            int v = (t >= off) ? sums[t - off] : 0;
            __syncthreads();
            sums[t] += v;
            __syncthreads();
        }
        int run = (t == 0) ? 0 : sums[t - 1];
        for (int i = base; i < lim; i++) {
            g_rowcur[i] = run;
            run += (int)g_deg[i];
        }
    }
}

// ---------------- counting-sort scatter ----------------
__global__ __launch_bounds__(512) void k_perm(const int* __restrict__ ei) {
    const int e = blockIdx.x * 512 + threadIdx.x;
    if (e >= N_EDGES) return;
    int r = ei[e];
    int p = atomicAdd(&g_rowcur[r], 1);
    g_srow[p] = r;
    g_scol[p] = ei[N_EDGES + e];
    g_sperm[p] = e;
}

// ---------------- per-layer node projection (1024 threads) ----------------
__global__ __launch_bounds__(1024, 1) void k_proj(const float* __restrict__ w,
                                                  const float* __restrict__ b1) {
    extern __shared__ float sm[];
    float* w_s = sm;            // [128][256]
    float* a_t = sm + 32768;    // [128 k][TP]
    const int t = threadIdx.x;
    const int n0 = blockIdx.x * 64;

    for (int i = t; i < 32768; i += 1024) {
        int k = i >> 8, jj = i & 255;
        int srcrow = (jj < 128) ? k : (128 + k);
        w_s[i] = w[srcrow * H + (jj & 127)];
    }
    for (int i = t; i < 8192; i += 1024) {
        int n = i >> 7, k = i & 127;
        int gi = n0 + n;
        a_t[k * TP + n] = (gi < N_NODES) ? g_h[gi * H + k] : 0.f;
    }
    for (int i = t; i < 64 * H; i += 1024) {
        int gi = n0 + (i >> 7);
        if (gi < N_NODES) g_agg[gi * H + (i & 127)] = 0.f;
    }
    if (t < 192) {
        int gi = n0 + t / 3;
        if (gi < N_NODES) g_posdelta[gi * 3 + t % 3] = 0.f;
    }
    __syncthreads();

    const int j0 = (t & 127) * 2;   // col pair (within 256)
    const int eh = t >> 7;          // 0..7 -> 8 nodes each
    const int nb = eh * 8;
    unsigned long long acc0[4], acc1[4];
#pragma unroll
    for (int p = 0; p < 4; p++) { acc0[p] = 0ull; acc1[p] = 0ull; }

#pragma unroll 4
    for (int k = 0; k < 128; k++) {
        float2 wp = *(const float2*)&w_s[k * 256 + j0];
        unsigned long long bd0 = dup2(wp.x), bd1 = dup2(wp.y);
        const float* ar = &a_t[k * TP + nb];
#pragma unroll
        for (int p = 0; p < 4; p++) {
            unsigned long long av = *(const unsigned long long*)&ar[2 * p];
            acc0[p] = fma2(av, bd0, acc0[p]);
            acc1[p] = fma2(av, bd1, acc1[p]);
        }
    }

    const int half = j0 >> 7;
    const int j = j0 & 127;
    float* outp = half ? g_P2 : g_P1;
    const float bb0 = half ? 0.f : b1[j];
    const float bb1 = half ? 0.f : b1[j + 1];
#pragma unroll
    for (int p = 0; p < 4; p++) {
        float2 a0 = unpack2(acc0[p]);
        float2 a1 = unpack2(acc1[p]);
        int n0g = n0 + nb + 2 * p;
        if (n0g < N_NODES) {
            float2 v = make_float2(a0.x + bb0, a1.x + bb1);
            *(float2*)&outp[n0g * H + j] = v;
        }
        if (n0g + 1 < N_NODES) {
            float2 v = make_float2(a0.y + bb0, a1.y + bb1);
            *(float2*)&outp[(n0g + 1) * H + j] = v;
        }
    }
}

// ---------------- fused edge kernel (1024 threads, sorted edges) ----------------
__global__ __launch_bounds__(1024, 1) void k_edge(
    const float* __restrict__ eattr,
    const float* __restrict__ w2, const float* __restrict__ b2,
    const float* __restrict__ cw1, const float* __restrict__ cb1,
    const float* __restrict__ cw2, const float* __restrict__ ew1) {
    extern __shared__ float sm[];
    float* w2_s  = sm;                // 16384
    float* c1_s  = w2_s + 16384;      // 16384
    float* b2_s  = c1_s + 16384;      // 128
    float* cb1_s = b2_s + 128;        // 128
    float* c2_s  = cb1_s + 128;       // 128
    float* wd2_s = c2_s + 128;        // 128
    float* wea_s = wd2_s + 128;       // 512
    float* hid_t = wea_s + 512;       // [128][TP]
    float* m_t   = hid_t + 128 * TP;  // [128][TP]
    float* d2_s  = m_t + 128 * TP;    // 64
    float* rel_s = d2_s + 64;         // 192
    float* ea_s  = rel_s + 192;       // 256
    float* wsum_s = ea_s + 256;       // 64
    float* wred  = wsum_s + 64;       // 128
    int* row_s = (int*)(wred + 128);  // 64
    int* col_s = row_s + 64;          // 64

    const int t = threadIdx.x;
    for (int i = t; i < 16384; i += 1024) { w2_s[i] = w2[i]; c1_s[i] = cw1[i]; }
    if (t < 128) {
        b2_s[t] = b2[t]; cb1_s[t] = cb1[t]; c2_s[t] = cw2[t];
        wd2_s[t] = ew1[256 * H + t];
    }
    if (t < 512) wea_s[t] = ew1[257 * H + t];
    __syncthreads();

    const int j0 = (t & 63) * 2;
    const int eh = t >> 6;          // 0..15, 4 edges each
    const int ebase = eh * 4;
    const int ntiles = (N_EDGES + NE_TILE - 1) / NE_TILE;

    for (int tile = blockIdx.x; tile < ntiles; tile += gridDim.x) {
        const int e0 = tile * NE_TILE;
        if (t < NE_TILE) {
            int sidx = e0 + t;
            int r = -1, c = 0, pe = 0;
            if (sidx < N_EDGES) { r = g_srow[sidx]; c = g_scol[sidx]; pe = g_sperm[sidx]; }
            row_s[t] = r; col_s[t] = c;
            float4 a = make_float4(0.f, 0.f, 0.f, 0.f);
            if (r >= 0) a = *(const float4*)&eattr[pe * 4];
            int rr = r < 0 ? 0 : r;
            float rx = g_pos[rr * 3 + 0] - g_pos[c * 3 + 0];
            float ry = g_pos[rr * 3 + 1] - g_pos[c * 3 + 1];
            float rz = g_pos[rr * 3 + 2] - g_pos[c * 3 + 2];
            rel_s[t * 3 + 0] = rx; rel_s[t * 3 + 1] = ry; rel_s[t * 3 + 2] = rz;
            d2_s[t] = rx * rx + ry * ry + rz * rz;
            ea_s[t * 4 + 0] = a.x; ea_s[t * 4 + 1] = a.y;
            ea_s[t * 4 + 2] = a.z; ea_s[t * 4 + 3] = a.w;
        }
        __syncthreads();

        // Phase A: hidden (8192 elems / 1024 threads = 8 reps)
#pragma unroll
        for (int rep = 0; rep < 8; rep++) {
            int idx = t + rep * 1024;
            int e = idx >> 7, j = idx & 127;
            int r = row_s[e], c = col_s[e];
            int rr = r < 0 ? 0 : r;
            float v = g_P1[rr * H + j] + g_P2[c * H + j] + d2_s[e] * wd2_s[j];
#pragma unroll
            for (int a2 = 0; a2 < 4; a2++) v += ea_s[e * 4 + a2] * wea_s[a2 * H + j];
            hid_t[j * TP + e] = silu_f(v);
        }
        __syncthreads();

        // Phase B: m = silu(hid @ W2 + b2)
        {
            unsigned long long acc0[2], acc1[2];
#pragma unroll
            for (int p = 0; p < 2; p++) { acc0[p] = 0ull; acc1[p] = 0ull; }
#pragma unroll 4
            for (int k = 0; k < 128; k++) {
                float2 wp = *(const float2*)&w2_s[k * H + j0];
                unsigned long long bd0 = dup2(wp.x), bd1 = dup2(wp.y);
                const float* hr = &hid_t[k * TP + ebase];
#pragma unroll
                for (int p = 0; p < 2; p++) {
                    unsigned long long av = *(const unsigned long long*)&hr[2 * p];
                    acc0[p] = fma2(av, bd0, acc0[p]);
                    acc1[p] = fma2(av, bd1, acc1[p]);
                }
            }
            float b0 = b2_s[j0], b1v = b2_s[j0 + 1];
#pragma unroll
            for (int p = 0; p < 2; p++) {
                float2 a0 = unpack2(acc0[p]);
                float2 a1 = unpack2(acc1[p]);
                float2 o0 = make_float2(silu_f(a0.x + b0), silu_f(a0.y + b0));
                float2 o1 = make_float2(silu_f(a1.x + b1v), silu_f(a1.y + b1v));
                *(float2*)&m_t[j0 * TP + ebase + 2 * p] = o0;
                *(float2*)&m_t[(j0 + 1) * TP + ebase + 2 * p] = o1;
            }
        }
        __syncthreads();

        // Phase C: w = silu(m@C1 + cb1) @ C2
        {
            unsigned long long acc0[2], acc1[2];
#pragma unroll
            for (int p = 0; p < 2; p++) { acc0[p] = 0ull; acc1[p] = 0ull; }
#pragma unroll 4
            for (int k = 0; k < 128; k++) {
                float2 wp = *(const float2*)&c1_s[k * H + j0];
                unsigned long long bd0 = dup2(wp.x), bd1 = dup2(wp.y);
                const float* mr = &m_t[k * TP + ebase];
#pragma unroll
                for (int p = 0; p < 2; p++) {
                    unsigned long long av = *(const unsigned long long*)&mr[2 * p];
                    acc0[p] = fma2(av, bd0, acc0[p]);
                    acc1[p] = fma2(av, bd1, acc1[p]);
                }
            }
            float cb0 = cb1_s[j0], cb1v = cb1_s[j0 + 1];
            float c20 = c2_s[j0], c21 = c2_s[j0 + 1];
            float part[4];
#pragma unroll
            for (int p = 0; p < 2; p++) {
                float2 a0 = unpack2(acc0[p]);
                float2 a1 = unpack2(acc1[p]);
                part[2 * p]     = silu_f(a0.x + cb0) * c20 + silu_f(a1.x + cb1v) * c21;
                part[2 * p + 1] = silu_f(a0.y + cb0) * c20 + silu_f(a1.y + cb1v) * c21;
            }
#pragma unroll
            for (int off = 16; off > 0; off >>= 1) {
#pragma unroll
                for (int e = 0; e < 4; e++)
                    part[e] += __shfl_xor_sync(0xffffffffu, part[e], off);
            }
            if ((t & 31) == 0) {
                int wsel = (t >> 5) & 1;
#pragma unroll
                for (int e = 0; e < 4; e++) wred[(ebase + e) * 2 + wsel] = part[e];
            }
        }
        __syncthreads();
        if (t < 64) wsum_s[t] = wred[t * 2] + wred[t * 2 + 1];
        __syncthreads();

        // Phase D: segment-scan scatter (8 edges per group, sorted rows)
        {
            const int j = t & 127;
            const int q = t >> 7;          // 0..7
            const int ebeg = q * 8;
            float acc = 0.f;
            int cur = row_s[ebeg];
#pragma unroll
            for (int i = 0; i < 8; i++) {
                int e = ebeg + i;
                int r = row_s[e];
                float v = m_t[j * TP + e];
                if (r != cur) {
                    if (cur >= 0) atomicAdd(&g_agg[cur * H + j], acc);
                    acc = 0.f;
                    cur = r;
                }
                acc += v;
            }
            if (cur >= 0) atomicAdd(&g_agg[cur * H + j], acc);
        }
        if (t < 192) {
            int e = t / 3, k = t % 3;
            int r = row_s[e];
            if (r >= 0)
                atomicAdd(&g_posdelta[r * 3 + k], rel_s[e * 3 + k] * wsum_s[e]);
        }
        __syncthreads();
    }
}

// ---------------- pos update ----------------
__global__ void k_pos() {
    const int idx = blockIdx.x * blockDim.x + threadIdx.x;
    if (idx >= N_NODES * 3) return;
    const int i = idx / 3;
    float d = fmaxf(g_deg[i], 1.0f);
    g_pos[idx] += g_posdelta[idx] / d;
}

// ---------------- node stage 1 (1024 threads) ----------------
__global__ __launch_bounds__(1024, 1) void k_node1(const float* __restrict__ w,
                                                   const float* __restrict__ b) {
    extern __shared__ float sm[];
    float* w_s = sm;              // [256][128]
    float* a_t = sm + 32768;      // [256][TP]
    const int t = threadIdx.x;
    const int n0 = blockIdx.x * 64;
    for (int i = t; i < 32768; i += 1024) w_s[i] = w[i];
    for (int i = t; i < 16384; i += 1024) {
        int n = i >> 8, k = i & 255;
        int gi = n0 + n;
        float v = 0.f;
        if (gi < N_NODES) v = (k < 128) ? g_h[gi * H + k] : g_agg[gi * H + (k - 128)];
        a_t[k * TP + n] = v;
    }
    __syncthreads();

    const int j0 = (t & 63) * 2;
    const int eh = t >> 6;        // 0..15, 4 nodes each
    const int nb = eh * 4;
    unsigned long long acc0[2], acc1[2];
#pragma unroll
    for (int p = 0; p < 2; p++) { acc0[p] = 0ull; acc1[p] = 0ull; }
#pragma unroll 4
    for (int k = 0; k < 256; k++) {
        float2 wp = *(const float2*)&w_s[k * H + j0];
        unsigned long long bd0 = dup2(wp.x), bd1 = dup2(wp.y);
        const float* ar = &a_t[k * TP + nb];
#pragma unroll
        for (int p = 0; p < 2; p++) {
            unsigned long long av = *(const unsigned long long*)&ar[2 * p];
            acc0[p] = fma2(av, bd0, acc0[p]);
            acc1[p] = fma2(av, bd1, acc1[p]);
        }
    }
    float b0 = b[j0], b1v = b[j0 + 1];
#pragma unroll
    for (int p = 0; p < 2; p++) {
        float2 a0 = unpack2(acc0[p]);
        float2 a1 = unpack2(acc1[p]);
        int n0g = n0 + nb + 2 * p;
        if (n0g < N_NODES) {
            float2 u = make_float2(silu_f(a0.x + b0), silu_f(a1.x + b1v));
            *(float2*)&g_U[n0g * H + j0] = u;
        }
        if (n0g + 1 < N_NODES) {
            float2 u = make_float2(silu_f(a0.y + b0), silu_f(a1.y + b1v));
            *(float2*)&g_U[(n0g + 1) * H + j0] = u;
        }
    }
}

// ---------------- node stage 2 (1024 threads) ----------------
__global__ __launch_bounds__(1024, 1) void k_node2(const float* __restrict__ w,
                                                   const float* __restrict__ b) {
    extern __shared__ float sm[];
    float* w_s = sm;              // [128][128]
    float* a_t = sm + 16384;      // [128][TP]
    const int t = threadIdx.x;
    const int n0 = blockIdx.x * 64;
    for (int i = t; i < 16384; i += 1024) w_s[i] = w[i];
    for (int i = t; i < 8192; i += 1024) {
        int n = i >> 7, k = i & 127;
        int gi = n0 + n;
        a_t[k * TP + n] = (gi < N_NODES) ? g_U[gi * H + k] : 0.f;
    }
    __syncthreads();

    const int j0 = (t & 63) * 2;
    const int eh = t >> 6;        // 0..15, 4 nodes each
    const int nb = eh * 4;
    unsigned long long acc0[2], acc1[2];
#pragma unroll
    for (int p = 0; p < 2; p++) { acc0[p] = 0ull; acc1[p] = 0ull; }
#pragma unroll 4
    for (int k = 0; k < 128; k++) {
        float2 wp = *(const float2*)&w_s[k * H + j0];
        unsigned long long bd0 = dup2(wp.x), bd1 = dup2(wp.y);
        const float* ar = &a_t[k * TP + nb];
#pragma unroll
        for (int p = 0; p < 2; p++) {
            unsigned long long av = *(const unsigned long long*)&ar[2 * p];
            acc0[p] = fma2(av, bd0, acc0[p]);
            acc1[p] = fma2(av, bd1, acc1[p]);
        }
    }
    float b0 = b[j0], b1v = b[j0 + 1];
#pragma unroll
    for (int p = 0; p < 2; p++) {
        float2 a0 = unpack2(acc0[p]);
        float2 a1 = unpack2(acc1[p]);
        int n0g = n0 + nb + 2 * p;
        if (n0g < N_NODES) {
            float2 hv = *(float2*)&g_h[n0g * H + j0];
            hv.x += a0.x + b0; hv.y += a1.x + b1v;
            *(float2*)&g_h[n0g * H + j0] = hv;
        }
        if (n0g + 1 < N_NODES) {
            float2 hv = *(float2*)&g_h[(n0g + 1) * H + j0];
            hv.x += a0.y + b0; hv.y += a1.y + b1v;
            *(float2*)&g_h[(n0g + 1) * H + j0] = hv;
        }
    }
}

// ---------------- pooling ----------------
__global__ __launch_bounds__(512) void k_pool() {
    __shared__ float red[512];
    const int g = blockIdx.x, t = threadIdx.x;
    const int j = t & 127, w = t >> 7;
    float s = 0.f;
    for (int n = w; n < NPG; n += 4) s += g_h[(g * NPG + n) * H + j];
    red[t] = s;
    __syncthreads();
    if (w == 0) {
        float tot = red[j] + red[128 + j] + red[256 + j] + red[384 + j];
        g_gfeat[g * 256 + j] = tot;
        g_gfeat[g * 256 + 128 + j] = tot * (1.f / (float)NPG);
    }
}

// ---------------- readout head ----------------
__global__ void k_head(const float* __restrict__ h1_w, const float* __restrict__ h1_b,
                       const float* __restrict__ h2_w, const float* __restrict__ h2_b,
                       const float* __restrict__ h3_w, const float* __restrict__ h3_b,
                       float* __restrict__ out) {
    __shared__ float gf[256], z1[128], z2[64];
    const int g = blockIdx.x, t = threadIdx.x;
    gf[t] = g_gfeat[g * 256 + t];
    gf[128 + t] = g_gfeat[g * 256 + 128 + t];
    __syncthreads();
    float a = h1_b[t];
    for (int k = 0; k < 256; k++) a += gf[k] * h1_w[k * 128 + t];
    z1[t] = fmaxf(a, 0.f);
    __syncthreads();
    if (t < 64) {
        float a2 = h2_b[t];
        for (int k = 0; k < 128; k++) a2 += z1[k] * h2_w[k * 64 + t];
        z2[t] = fmaxf(a2, 0.f);
    }
    __syncthreads();
    if (t == 0) {
        float a3 = h3_b[0];
        for (int k = 0; k < 64; k++) a3 += z2[k] * h3_w[k];
        out[g] = a3;
    }
}

// ---------------- launch ----------------
extern "C" void kernel_launch(void* const* d_in, const int* in_sizes, int n_in,
                              void* d_out, int out_size) {
    const float* x     = (const float*)d_in[0];
    const float* pos   = (const float*)d_in[1];
    const int*   ei    = (const int*)d_in[2];
    const float* eattr = (const float*)d_in[3];
    const float* Wp    = (const float*)d_in[6];
    const float* bp    = (const float*)d_in[7];
    const float* Wl    = (const float*)d_in[8];
    const float* bl    = (const float*)d_in[9];
    const float* gamma = (const float*)d_in[10];
    const float* beta  = (const float*)d_in[11];
    const float* e_w1  = (const float*)d_in[12];
    const float* e_b1  = (const float*)d_in[13];
    const float* e_w2  = (const float*)d_in[14];
    const float* e_b2  = (const float*)d_in[15];
    const float* c_w1  = (const float*)d_in[16];
    const float* c_b1  = (const float*)d_in[17];
    const float* c_w2  = (const float*)d_in[18];
    const float* n_w1  = (const float*)d_in[19];
    const float* n_b1  = (const float*)d_in[20];
    const float* n_w2  = (const float*)d_in[21];
    const float* n_b2  = (const float*)d_in[22];
    const float* h1_w  = (const float*)d_in[23];
    const float* h1_b  = (const float*)d_in[24];
    const float* h2_w  = (const float*)d_in[25];
    const float* h2_b  = (const float*)d_in[26];
    const float* h3_w  = (const float*)d_in[27];
    const float* h3_b  = (const float*)d_in[28];
    float* out = (float*)d_out;

    const int PROJ_SMEM = (32768 + 128 * TP) * 4;
    const int EDGE_SMEM = (16384 * 2 + 128 * 5 + 512 + 2 * 128 * TP
                           + 64 + 192 + 256 + 64 + 128 + 128) * 4;
    const int N1_SMEM = (32768 + 256 * TP) * 4;
    const int N2_SMEM = (16384 + 128 * TP) * 4;
    cudaFuncSetAttribute(k_proj,  cudaFuncAttributeMaxDynamicSharedMemorySize, PROJ_SMEM);
    cudaFuncSetAttribute(k_edge,  cudaFuncAttributeMaxDynamicSharedMemorySize, EDGE_SMEM);
    cudaFuncSetAttribute(k_node1, cudaFuncAttributeMaxDynamicSharedMemorySize, N1_SMEM);
    cudaFuncSetAttribute(k_node2, cudaFuncAttributeMaxDynamicSharedMemorySize, N2_SMEM);

    const int nblocks64 = (N_NODES + 63) / 64;   // 782

    k_embed<<<N_NODES, 128>>>(x, pos, Wp, bp, Wl, bl);
    k_stats_deg<<<256 + DEG_BLOCKS, 512>>>(ei);
    k_bnapply_scan<<<BNA_BLOCKS + 1, 512>>>(gamma, beta);

    for (int l = 0; l < NLAYERS; l++) {
        k_proj<<<nblocks64, 1024, PROJ_SMEM>>>(e_w1 + l * 261 * H, e_b1 + l * H);
        if (l == 0) k_perm<<<(N_EDGES + 511) / 512, 512>>>(ei);
        k_edge<<<148, 1024, EDGE_SMEM>>>(eattr,
                                         e_w2 + l * H * H, e_b2 + l * H,
                                         c_w1 + l * H * H, c_b1 + l * H,
                                         c_w2 + l * H, e_w1 + l * 261 * H);
        k_node1<<<nblocks64, 1024, N1_SMEM>>>(n_w1 + l * 256 * H, n_b1 + l * H);
        k_node2<<<nblocks64, 1024, N2_SMEM>>>(n_w2 + l * H * H, n_b2 + l * H);
        k_pos<<<(N_NODES * 3 + 511) / 512, 512>>>();
    }

    k_pool<<<G_GRAPHS, 512>>>();
    k_head<<<G_GRAPHS, 128>>>(h1_w, h1_b, h2_w, h2_b, h3_w, h3_b, out);
}

// round 5
// speedup vs baseline: 1.5780x; 1.5161x over previous
#include <cuda_runtime.h>
#include <cuda_bf16.h>

#define N_NODES 50000
#define N_EDGES 500000
#define H 128
#define G_GRAPHS 100
#define NPG 500
#define NPROT 400
#define PN 35
#define LN 11
#define NLAYERS 4
#define EPS 1e-5f
#define NE_TILE 64
#define TP 66   // transposed smem row pad (floats) — node/proj kernels

// ---------------- scratch ----------------
__device__ float g_h[N_NODES * H];
__device__ float g_P1[N_NODES * H];
__device__ float g_P2[N_NODES * H];
__device__ float g_agg[N_NODES * H];
__device__ float g_U[N_NODES * H];
__device__ float g_pos[N_NODES * 3];
__device__ float g_posdelta[N_NODES * 3];
__device__ float g_deg[N_NODES];
__device__ float g_bnstats[2 * H];
__device__ float g_gfeat[G_GRAPHS * 2 * H];
__device__ int g_rowcur[N_NODES];
__device__ int g_srow[N_EDGES];
__device__ int g_scol[N_EDGES];
__device__ int g_sperm[N_EDGES];

__device__ __forceinline__ float silu_f(float x) {
    return x / (1.f + __expf(-x));
}

// ---- packed f32x2 helpers (FFMA2 path for node/proj kernels) ----
__device__ __forceinline__ unsigned long long fma2(unsigned long long a,
                                                   unsigned long long b,
                                                   unsigned long long c) {
    unsigned long long d;
    asm("fma.rn.f32x2 %0, %1, %2, %3;" : "=l"(d) : "l"(a), "l"(b), "l"(c));
    return d;
}
__device__ __forceinline__ unsigned long long dup2(float x) {
    unsigned long long d;
    unsigned int xi = __float_as_uint(x);
    asm("mov.b64 %0, {%1, %1};" : "=l"(d) : "r"(xi));
    return d;
}
__device__ __forceinline__ float2 unpack2(unsigned long long v) {
    unsigned int lo, hi;
    asm("mov.b64 {%0, %1}, %2;" : "=r"(lo), "=r"(hi) : "l"(v));
    float2 r;
    r.x = __uint_as_float(lo);
    r.y = __uint_as_float(hi);
    return r;
}

// ---- tf32 mma helpers ----
__device__ __forceinline__ float tf32f(float f) {
    unsigned int u;
    asm("cvt.rna.tf32.f32 %0, %1;" : "=r"(u) : "f"(f));
    return __uint_as_float(u);
}
__device__ __forceinline__ void mma_tf32(float* c, const uint4& a, const uint2& b) {
    asm volatile(
        "mma.sync.aligned.m16n8k8.row.col.f32.tf32.tf32.f32 "
        "{%0,%1,%2,%3}, {%4,%5,%6,%7}, {%8,%9}, {%0,%1,%2,%3};"
        : "+f"(c[0]), "+f"(c[1]), "+f"(c[2]), "+f"(c[3])
        : "r"(a.x), "r"(a.y), "r"(a.z), "r"(a.w), "r"(b.x), "r"(b.y));
}
// A-fragment flat index for value at (row e in 0..63, col k in 0..127)
__device__ __forceinline__ int fragA_idx(int e, int k) {
    int lane = ((e & 7) << 2) | (k & 3);
    int reg = ((e >> 3) & 1) | (((k >> 2) & 1) << 1);
    return ((((e >> 4) * 16 + (k >> 3)) << 7)) + (lane << 2) + reg;
}

// ---------------- K1: embed ----------------
__global__ void k_embed(const float* __restrict__ x, const float* __restrict__ pos_in,
                        const float* __restrict__ Wp, const float* __restrict__ bp,
                        const float* __restrict__ Wl, const float* __restrict__ bl) {
    __shared__ float xs[PN];
    const int i = blockIdx.x;
    const int t = threadIdx.x;
    if (t < PN) xs[t] = x[i * PN + t];
    if (t == 0) g_deg[i] = 0.f;
    if (t < 3) g_pos[i * 3 + t] = pos_in[i * 3 + t];
    if (i == 0 && t < H) { g_bnstats[t] = 0.f; g_bnstats[H + t] = 0.f; }
    __syncthreads();
    const bool isp = (i % NPG) < NPROT;
    const float* W = isp ? Wp : Wl;
    const float* b = isp ? bp : bl;
    const int nk = isp ? PN : LN;
    float acc = b[t];
    for (int k = 0; k < nk; k++) acc += xs[k] * W[k * H + t];
    g_h[i * H + t] = acc;
}

// ---------------- K2: bnstats + degree ----------------
#define DEG_BLOCKS ((N_EDGES + 511) / 512)
__global__ __launch_bounds__(512) void k_stats_deg(const int* __restrict__ ei) {
    const int t = threadIdx.x;
    if (blockIdx.x < 256) {
        const int j = t & 127;
        const int g2 = t >> 7;
        float s = 0.f, s2 = 0.f;
        for (int i = blockIdx.x * 4 + g2; i < N_NODES; i += 1024) {
            float v = g_h[i * H + j];
            s += v; s2 += v * v;
        }
        atomicAdd(&g_bnstats[j], s);
        atomicAdd(&g_bnstats[H + j], s2);
    } else {
        const int e = (blockIdx.x - 256) * 512 + t;
        if (e < N_EDGES) atomicAdd(&g_deg[ei[e]], 1.0f);
    }
}

// ---------------- K3: bnapply + degree scan ----------------
#define BNA_BLOCKS ((N_NODES * H) / 512)
__global__ __launch_bounds__(512) void k_bnapply_scan(const float* __restrict__ gamma,
                                                      const float* __restrict__ beta) {
    const int t = threadIdx.x;
    if (blockIdx.x < BNA_BLOCKS) {
        const int idx = blockIdx.x * 512 + t;
        const int j = idx & (H - 1);
        const float inv_n = 1.f / (float)N_NODES;
        float mu = g_bnstats[j] * inv_n;
        float var = g_bnstats[H + j] * inv_n - mu * mu;
        g_h[idx] = (g_h[idx] - mu) * rsqrtf(var + EPS) * gamma[j] + beta[j];
    } else {
        __shared__ int sums[512];
        const int chunk = 98;
        int base = t * chunk;
        int lim = min(base + chunk, N_NODES);
        int s = 0;
        for (int i = base; i < lim; i++) s += (int)g_deg[i];
        sums[t] = s;
        __syncthreads();
        for (int off = 1; off < 512; off <<= 1) {
            int v = (t >= off) ? sums[t - off] : 0;
            __syncthreads();
            sums[t] += v;
            __syncthreads();
        }
        int run = (t == 0) ? 0 : sums[t - 1];
        for (int i = base; i < lim; i++) {
            g_rowcur[i] = run;
            run += (int)g_deg[i];
        }
    }
}

// ---------------- counting-sort scatter ----------------
__global__ __launch_bounds__(512) void k_perm(const int* __restrict__ ei) {
    const int e = blockIdx.x * 512 + threadIdx.x;
    if (e >= N_EDGES) return;
    int r = ei[e];
    int p = atomicAdd(&g_rowcur[r], 1);
    g_srow[p] = r;
    g_scol[p] = ei[N_EDGES + e];
    g_sperm[p] = e;
}

// ---------------- per-layer node projection (FFMA2, 1024 thr) ----------------
__global__ __launch_bounds__(1024, 1) void k_proj(const float* __restrict__ w,
                                                  const float* __restrict__ b1) {
    extern __shared__ float sm[];
    float* w_s = sm;            // [128][256]
    float* a_t = sm + 32768;    // [128 k][TP]
    const int t = threadIdx.x;
    const int n0 = blockIdx.x * 64;

    for (int i = t; i < 32768; i += 1024) {
        int k = i >> 8, jj = i & 255;
        int srcrow = (jj < 128) ? k : (128 + k);
        w_s[i] = w[srcrow * H + (jj & 127)];
    }
    for (int i = t; i < 8192; i += 1024) {
        int n = i >> 7, k = i & 127;
        int gi = n0 + n;
        a_t[k * TP + n] = (gi < N_NODES) ? g_h[gi * H + k] : 0.f;
    }
    for (int i = t; i < 64 * H; i += 1024) {
        int gi = n0 + (i >> 7);
        if (gi < N_NODES) g_agg[gi * H + (i & 127)] = 0.f;
    }
    if (t < 192) {
        int gi = n0 + t / 3;
        if (gi < N_NODES) g_posdelta[gi * 3 + t % 3] = 0.f;
    }
    __syncthreads();

    const int j0 = (t & 127) * 2;
    const int eh = t >> 7;
    const int nb = eh * 8;
    unsigned long long acc0[4], acc1[4];
#pragma unroll
    for (int p = 0; p < 4; p++) { acc0[p] = 0ull; acc1[p] = 0ull; }

#pragma unroll 4
    for (int k = 0; k < 128; k++) {
        float2 wp = *(const float2*)&w_s[k * 256 + j0];
        unsigned long long bd0 = dup2(wp.x), bd1 = dup2(wp.y);
        const float* ar = &a_t[k * TP + nb];
#pragma unroll
        for (int p = 0; p < 4; p++) {
            unsigned long long av = *(const unsigned long long*)&ar[2 * p];
            acc0[p] = fma2(av, bd0, acc0[p]);
            acc1[p] = fma2(av, bd1, acc1[p]);
        }
    }

    const int half = j0 >> 7;
    const int j = j0 & 127;
    float* outp = half ? g_P2 : g_P1;
    const float bb0 = half ? 0.f : b1[j];
    const float bb1 = half ? 0.f : b1[j + 1];
#pragma unroll
    for (int p = 0; p < 4; p++) {
        float2 a0 = unpack2(acc0[p]);
        float2 a1 = unpack2(acc1[p]);
        int n0g = n0 + nb + 2 * p;
        if (n0g < N_NODES) {
            float2 v = make_float2(a0.x + bb0, a1.x + bb1);
            *(float2*)&outp[n0g * H + j] = v;
        }
        if (n0g + 1 < N_NODES) {
            float2 v = make_float2(a0.y + bb0, a1.y + bb1);
            *(float2*)&outp[(n0g + 1) * H + j] = v;
        }
    }
}

// ---------------- fused edge kernel: tf32 mma for GEMM phases ----------------
__global__ __launch_bounds__(1024, 1) void k_edge(
    const float* __restrict__ eattr,
    const float* __restrict__ w2, const float* __restrict__ b2,
    const float* __restrict__ cw1, const float* __restrict__ cb1,
    const float* __restrict__ cw2, const float* __restrict__ ew1) {
    extern __shared__ float sm[];
    float* w2F   = sm;                 // 16384 (B-fragment order)
    float* c1F   = w2F + 16384;        // 16384
    float* hidF  = c1F + 16384;        // 8192  (A-fragment order)
    float* mF    = hidF + 8192;        // 8192
    float* b2_s  = mF + 8192;          // 128
    float* cb1_s = b2_s + 128;         // 128
    float* c2_s  = cb1_s + 128;        // 128
    float* wd2_s = c2_s + 128;         // 128
    float* wea_s = wd2_s + 128;        // 512
    float* d2_s  = wea_s + 512;        // 64
    float* rel_s = d2_s + 64;          // 192
    float* ea_s  = rel_s + 192;        // 256
    float* wsum_s = ea_s + 256;        // 64
    int* row_s = (int*)(wsum_s + 64);  // 64
    int* col_s = row_s + 64;           // 64

    const int t = threadIdx.x;
    // prepack weights into B-fragment order (tf32 rounded)
    for (int i = t; i < 16384; i += 1024) {
        int r = i & 1;
        int lanei = (i >> 1) & 31;
        int ks = (i >> 6) & 15;
        int nt = i >> 10;
        int k = ks * 8 + (lanei & 3) + r * 4;
        int n = nt * 8 + (lanei >> 2);
        w2F[i] = tf32f(w2[k * H + n]);
        c1F[i] = tf32f(cw1[k * H + n]);
    }
    if (t < 128) {
        b2_s[t] = b2[t]; cb1_s[t] = cb1[t]; c2_s[t] = cw2[t];
        wd2_s[t] = ew1[256 * H + t];
    }
    if (t >= 128 && t < 640) wea_s[t - 128] = ew1[257 * H + (t - 128)];
    __syncthreads();

    const int w = t >> 5;
    const int lane = t & 31;
    const int mt = w >> 3;         // 0..3
    const int nt0 = (w & 7) * 2;   // 0..14
    const int grp = lane >> 2;     // 0..7
    const int thr = lane & 3;      // 0..3
    const int ntiles = (N_EDGES + NE_TILE - 1) / NE_TILE;

    for (int tile = blockIdx.x; tile < ntiles; tile += gridDim.x) {
        const int e0 = tile * NE_TILE;
        if (t < NE_TILE) {
            wsum_s[t] = 0.f;
            int sidx = e0 + t;
            int r = -1, c = 0, pe = 0;
            if (sidx < N_EDGES) { r = g_srow[sidx]; c = g_scol[sidx]; pe = g_sperm[sidx]; }
            row_s[t] = r; col_s[t] = c;
            float4 a = make_float4(0.f, 0.f, 0.f, 0.f);
            if (r >= 0) a = *(const float4*)&eattr[pe * 4];
            int rr = r < 0 ? 0 : r;
            float rx = g_pos[rr * 3 + 0] - g_pos[c * 3 + 0];
            float ry = g_pos[rr * 3 + 1] - g_pos[c * 3 + 1];
            float rz = g_pos[rr * 3 + 2] - g_pos[c * 3 + 2];
            rel_s[t * 3 + 0] = rx; rel_s[t * 3 + 1] = ry; rel_s[t * 3 + 2] = rz;
            d2_s[t] = rx * rx + ry * ry + rz * rz;
            ea_s[t * 4 + 0] = a.x; ea_s[t * 4 + 1] = a.y;
            ea_s[t * 4 + 2] = a.z; ea_s[t * 4 + 3] = a.w;
        }
        __syncthreads();

        // Phase A: hidden -> hidF (A-fragment order, tf32)
#pragma unroll
        for (int rep = 0; rep < 8; rep++) {
            int idx = t + rep * 1024;
            int e = idx >> 7, j = idx & 127;
            int r = row_s[e], c = col_s[e];
            int rr = r < 0 ? 0 : r;
            float v = g_P1[rr * H + j] + g_P2[c * H + j] + d2_s[e] * wd2_s[j];
#pragma unroll
            for (int a2 = 0; a2 < 4; a2++) v += ea_s[e * 4 + a2] * wea_s[a2 * H + j];
            hidF[fragA_idx(e, j)] = tf32f(silu_f(v));
        }
        __syncthreads();

        // Phase B: m = silu(hid @ W2 + b2)  — tf32 mma
        {
            float c0[4], c1[4];
            {
                int jc0 = nt0 * 8 + 2 * thr;
                int jc1 = (nt0 + 1) * 8 + 2 * thr;
                c0[0] = b2_s[jc0]; c0[1] = b2_s[jc0 + 1]; c0[2] = c0[0]; c0[3] = c0[1];
                c1[0] = b2_s[jc1]; c1[1] = b2_s[jc1 + 1]; c1[2] = c1[0]; c1[3] = c1[1];
            }
#pragma unroll
            for (int ks = 0; ks < 16; ks++) {
                uint4 a = *(const uint4*)&hidF[(((mt * 16 + ks) << 5) + lane) << 2];
                uint2 b0 = *(const uint2*)&w2F[((((nt0) * 16 + ks) << 5) + lane) << 1];
                uint2 b1 = *(const uint2*)&w2F[((((nt0 + 1) * 16 + ks) << 5) + lane) << 1];
                mma_tf32(c0, a, b0);
                mma_tf32(c1, a, b1);
            }
            int ee0 = mt * 16 + grp, ee1 = ee0 + 8;
            int j00 = nt0 * 8 + 2 * thr;
            int j10 = (nt0 + 1) * 8 + 2 * thr;
            mF[fragA_idx(ee0, j00)]     = tf32f(silu_f(c0[0]));
            mF[fragA_idx(ee0, j00 + 1)] = tf32f(silu_f(c0[1]));
            mF[fragA_idx(ee1, j00)]     = tf32f(silu_f(c0[2]));
            mF[fragA_idx(ee1, j00 + 1)] = tf32f(silu_f(c0[3]));
            mF[fragA_idx(ee0, j10)]     = tf32f(silu_f(c1[0]));
            mF[fragA_idx(ee0, j10 + 1)] = tf32f(silu_f(c1[1]));
            mF[fragA_idx(ee1, j10)]     = tf32f(silu_f(c1[2]));
            mF[fragA_idx(ee1, j10 + 1)] = tf32f(silu_f(c1[3]));
        }
        __syncthreads();

        // Phase C: w = silu(m@C1 + cb1) @ C2 — tf32 mma + reduction
        {
            float c0[4], c1[4];
            int j00 = nt0 * 8 + 2 * thr;
            int j10 = (nt0 + 1) * 8 + 2 * thr;
            c0[0] = cb1_s[j00]; c0[1] = cb1_s[j00 + 1]; c0[2] = c0[0]; c0[3] = c0[1];
            c1[0] = cb1_s[j10]; c1[1] = cb1_s[j10 + 1]; c1[2] = c1[0]; c1[3] = c1[1];
#pragma unroll
            for (int ks = 0; ks < 16; ks++) {
                uint4 a = *(const uint4*)&mF[(((mt * 16 + ks) << 5) + lane) << 2];
                uint2 b0 = *(const uint2*)&c1F[((((nt0) * 16 + ks) << 5) + lane) << 1];
                uint2 b1 = *(const uint2*)&c1F[((((nt0 + 1) * 16 + ks) << 5) + lane) << 1];
                mma_tf32(c0, a, b0);
                mma_tf32(c1, a, b1);
            }
            float sl = silu_f(c0[0]) * c2_s[j00] + silu_f(c0[1]) * c2_s[j00 + 1]
                     + silu_f(c1[0]) * c2_s[j10] + silu_f(c1[1]) * c2_s[j10 + 1];
            float sh = silu_f(c0[2]) * c2_s[j00] + silu_f(c0[3]) * c2_s[j00 + 1]
                     + silu_f(c1[2]) * c2_s[j10] + silu_f(c1[3]) * c2_s[j10 + 1];
            sl += __shfl_xor_sync(0xffffffffu, sl, 1);
            sl += __shfl_xor_sync(0xffffffffu, sl, 2);
            sh += __shfl_xor_sync(0xffffffffu, sh, 1);
            sh += __shfl_xor_sync(0xffffffffu, sh, 2);
            if (thr == 0) {
                atomicAdd(&wsum_s[mt * 16 + grp], sl);
                atomicAdd(&wsum_s[mt * 16 + grp + 8], sh);
            }
        }
        __syncthreads();

        // Phase D: segment-scan scatter of m into agg; posdelta from wsum
        {
            const int j = t & 127;
            const int q = t >> 7;          // 0..7
            const int ebeg = q * 8;
            float acc = 0.f;
            int cur = row_s[ebeg];
#pragma unroll
            for (int i = 0; i < 8; i++) {
                int e = ebeg + i;
                int r = row_s[e];
                float v = mF[fragA_idx(e, j)];
                if (r != cur) {
                    if (cur >= 0) atomicAdd(&g_agg[cur * H + j], acc);
                    acc = 0.f;
                    cur = r;
                }
                acc += v;
            }
            if (cur >= 0) atomicAdd(&g_agg[cur * H + j], acc);
        }
        if (t < 192) {
            int e = t / 3, k = t % 3;
            int r = row_s[e];
            if (r >= 0)
                atomicAdd(&g_posdelta[r * 3 + k], rel_s[e * 3 + k] * wsum_s[e]);
        }
        __syncthreads();
    }
}

// ---------------- pos update ----------------
__global__ void k_pos() {
    const int idx = blockIdx.x * blockDim.x + threadIdx.x;
    if (idx >= N_NODES * 3) return;
    const int i = idx / 3;
    float d = fmaxf(g_deg[i], 1.0f);
    g_pos[idx] += g_posdelta[idx] / d;
}

// ---------------- node stage 1 (FFMA2, 1024 thr) ----------------
__global__ __launch_bounds__(1024, 1) void k_node1(const float* __restrict__ w,
                                                   const float* __restrict__ b) {
    extern __shared__ float sm[];
    float* w_s = sm;              // [256][128]
    float* a_t = sm + 32768;      // [256][TP]
    const int t = threadIdx.x;
    const int n0 = blockIdx.x * 64;
    for (int i = t; i < 32768; i += 1024) w_s[i] = w[i];
    for (int i = t; i < 16384; i += 1024) {
        int n = i >> 8, k = i & 255;
        int gi = n0 + n;
        float v = 0.f;
        if (gi < N_NODES) v = (k < 128) ? g_h[gi * H + k] : g_agg[gi * H + (k - 128)];
        a_t[k * TP + n] = v;
    }
    __syncthreads();

    const int j0 = (t & 63) * 2;
    const int eh = t >> 6;
    const int nb = eh * 4;
    unsigned long long acc0[2], acc1[2];
#pragma unroll
    for (int p = 0; p < 2; p++) { acc0[p] = 0ull; acc1[p] = 0ull; }
#pragma unroll 4
    for (int k = 0; k < 256; k++) {
        float2 wp = *(const float2*)&w_s[k * H + j0];
        unsigned long long bd0 = dup2(wp.x), bd1 = dup2(wp.y);
        const float* ar = &a_t[k * TP + nb];
#pragma unroll
        for (int p = 0; p < 2; p++) {
            unsigned long long av = *(const unsigned long long*)&ar[2 * p];
            acc0[p] = fma2(av, bd0, acc0[p]);
            acc1[p] = fma2(av, bd1, acc1[p]);
        }
    }
    float b0 = b[j0], b1v = b[j0 + 1];
#pragma unroll
    for (int p = 0; p < 2; p++) {
        float2 a0 = unpack2(acc0[p]);
        float2 a1 = unpack2(acc1[p]);
        int n0g = n0 + nb + 2 * p;
        if (n0g < N_NODES) {
            float2 u = make_float2(silu_f(a0.x + b0), silu_f(a1.x + b1v));
            *(float2*)&g_U[n0g * H + j0] = u;
        }
        if (n0g + 1 < N_NODES) {
            float2 u = make_float2(silu_f(a0.y + b0), silu_f(a1.y + b1v));
            *(float2*)&g_U[(n0g + 1) * H + j0] = u;
        }
    }
}

// ---------------- node stage 2 (FFMA2, 1024 thr) ----------------
__global__ __launch_bounds__(1024, 1) void k_node2(const float* __restrict__ w,
                                                   const float* __restrict__ b) {
    extern __shared__ float sm[];
    float* w_s = sm;              // [128][128]
    float* a_t = sm + 16384;      // [128][TP]
    const int t = threadIdx.x;
    const int n0 = blockIdx.x * 64;
    for (int i = t; i < 16384; i += 1024) w_s[i] = w[i];
    for (int i = t; i < 8192; i += 1024) {
        int n = i >> 7, k = i & 127;
        int gi = n0 + n;
        a_t[k * TP + n] = (gi < N_NODES) ? g_U[gi * H + k] : 0.f;
    }
    __syncthreads();

    const int j0 = (t & 63) * 2;
    const int eh = t >> 6;
    const int nb = eh * 4;
    unsigned long long acc0[2], acc1[2];
#pragma unroll
    for (int p = 0; p < 2; p++) { acc0[p] = 0ull; acc1[p] = 0ull; }
#pragma unroll 4
    for (int k = 0; k < 128; k++) {
        float2 wp = *(const float2*)&w_s[k * H + j0];
        unsigned long long bd0 = dup2(wp.x), bd1 = dup2(wp.y);
        const float* ar = &a_t[k * TP + nb];
#pragma unroll
        for (int p = 0; p < 2; p++) {
            unsigned long long av = *(const unsigned long long*)&ar[2 * p];
            acc0[p] = fma2(av, bd0, acc0[p]);
            acc1[p] = fma2(av, bd1, acc1[p]);
        }
    }
    float b0 = b[j0], b1v = b[j0 + 1];
#pragma unroll
    for (int p = 0; p < 2; p++) {
        float2 a0 = unpack2(acc0[p]);
        float2 a1 = unpack2(acc1[p]);
        int n0g = n0 + nb + 2 * p;
        if (n0g < N_NODES) {
            float2 hv = *(float2*)&g_h[n0g * H + j0];
            hv.x += a0.x + b0; hv.y += a1.x + b1v;
            *(float2*)&g_h[n0g * H + j0] = hv;
        }
        if (n0g + 1 < N_NODES) {
            float2 hv = *(float2*)&g_h[(n0g + 1) * H + j0];
            hv.x += a0.y + b0; hv.y += a1.y + b1v;
            *(float2*)&g_h[(n0g + 1) * H + j0] = hv;
        }
    }
}

// ---------------- pooling ----------------
__global__ __launch_bounds__(512) void k_pool() {
    __shared__ float red[512];
    const int g = blockIdx.x, t = threadIdx.x;
    const int j = t & 127, w = t >> 7;
    float s = 0.f;
    for (int n = w; n < NPG; n += 4) s += g_h[(g * NPG + n) * H + j];
    red[t] = s;
    __syncthreads();
    if (w == 0) {
        float tot = red[j] + red[128 + j] + red[256 + j] + red[384 + j];
        g_gfeat[g * 256 + j] = tot;
        g_gfeat[g * 256 + 128 + j] = tot * (1.f / (float)NPG);
    }
}

// ---------------- readout head ----------------
__global__ void k_head(const float* __restrict__ h1_w, const float* __restrict__ h1_b,
                       const float* __restrict__ h2_w, const float* __restrict__ h2_b,
                       const float* __restrict__ h3_w, const float* __restrict__ h3_b,
                       float* __restrict__ out) {
    __shared__ float gf[256], z1[128], z2[64];
    const int g = blockIdx.x, t = threadIdx.x;
    gf[t] = g_gfeat[g * 256 + t];
    gf[128 + t] = g_gfeat[g * 256 + 128 + t];
    __syncthreads();
    float a = h1_b[t];
    for (int k = 0; k < 256; k++) a += gf[k] * h1_w[k * 128 + t];
    z1[t] = fmaxf(a, 0.f);
    __syncthreads();
    if (t < 64) {
        float a2 = h2_b[t];
        for (int k = 0; k < 128; k++) a2 += z1[k] * h2_w[k * 64 + t];
        z2[t] = fmaxf(a2, 0.f);
    }
    __syncthreads();
    if (t == 0) {
        float a3 = h3_b[0];
        for (int k = 0; k < 64; k++) a3 += z2[k] * h3_w[k];
        out[g] = a3;
    }
}

// ---------------- launch ----------------
extern "C" void kernel_launch(void* const* d_in, const int* in_sizes, int n_in,
                              void* d_out, int out_size) {
    const float* x     = (const float*)d_in[0];
    const float* pos   = (const float*)d_in[1];
    const int*   ei    = (const int*)d_in[2];
    const float* eattr = (const float*)d_in[3];
    const float* Wp    = (const float*)d_in[6];
    const float* bp    = (const float*)d_in[7];
    const float* Wl    = (const float*)d_in[8];
    const float* bl    = (const float*)d_in[9];
    const float* gamma = (const float*)d_in[10];
    const float* beta  = (const float*)d_in[11];
    const float* e_w1  = (const float*)d_in[12];
    const float* e_b1  = (const float*)d_in[13];
    const float* e_w2  = (const float*)d_in[14];
    const float* e_b2  = (const float*)d_in[15];
    const float* c_w1  = (const float*)d_in[16];
    const float* c_b1  = (const float*)d_in[17];
    const float* c_w2  = (const float*)d_in[18];
    const float* n_w1  = (const float*)d_in[19];
    const float* n_b1  = (const float*)d_in[20];
    const float* n_w2  = (const float*)d_in[21];
    const float* n_b2  = (const float*)d_in[22];
    const float* h1_w  = (const float*)d_in[23];
    const float* h1_b  = (const float*)d_in[24];
    const float* h2_w  = (const float*)d_in[25];
    const float* h2_b  = (const float*)d_in[26];
    const float* h3_w  = (const float*)d_in[27];
    const float* h3_b  = (const float*)d_in[28];
    float* out = (float*)d_out;

    const int PROJ_SMEM = (32768 + 128 * TP) * 4;
    const int EDGE_SMEM = (16384 + 16384 + 8192 + 8192
                           + 128 * 4 + 512 + 64 + 192 + 256 + 64 + 64 + 64) * 4;
    const int N1_SMEM = (32768 + 256 * TP) * 4;
    const int N2_SMEM = (16384 + 128 * TP) * 4;
    cudaFuncSetAttribute(k_proj,  cudaFuncAttributeMaxDynamicSharedMemorySize, PROJ_SMEM);
    cudaFuncSetAttribute(k_edge,  cudaFuncAttributeMaxDynamicSharedMemorySize, EDGE_SMEM);
    cudaFuncSetAttribute(k_node1, cudaFuncAttributeMaxDynamicSharedMemorySize, N1_SMEM);
    cudaFuncSetAttribute(k_node2, cudaFuncAttributeMaxDynamicSharedMemorySize, N2_SMEM);

    const int nblocks64 = (N_NODES + 63) / 64;   // 782

    k_embed<<<N_NODES, 128>>>(x, pos, Wp, bp, Wl, bl);
    k_stats_deg<<<256 + DEG_BLOCKS, 512>>>(ei);
    k_bnapply_scan<<<BNA_BLOCKS + 1, 512>>>(gamma, beta);

    for (int l = 0; l < NLAYERS; l++) {
        k_proj<<<nblocks64, 1024, PROJ_SMEM>>>(e_w1 + l * 261 * H, e_b1 + l * H);
        if (l == 0) k_perm<<<(N_EDGES + 511) / 512, 512>>>(ei);
        k_edge<<<148, 1024, EDGE_SMEM>>>(eattr,
                                         e_w2 + l * H * H, e_b2 + l * H,
                                         c_w1 + l * H * H, c_b1 + l * H,
                                         c_w2 + l * H, e_w1 + l * 261 * H);
        k_node1<<<nblocks64, 1024, N1_SMEM>>>(n_w1 + l * 256 * H, n_b1 + l * H);
        k_node2<<<nblocks64, 1024, N2_SMEM>>>(n_w2 + l * H * H, n_b2 + l * H);
        k_pos<<<(N_NODES * 3 + 511) / 512, 512>>>();
    }

    k_pool<<<G_GRAPHS, 512>>>();
    k_head<<<G_GRAPHS, 128>>>(h1_w, h1_b, h2_w, h2_b, h3_w, h3_b, out);
}